// round 12
// baseline (speedup 1.0000x reference)
#include <cuda_runtime.h>
#include <cstdint>
#include <math.h>

// ---------------- problem constants ----------------
#define E_EXPERTS 8
#define D_MODEL   1024
#define D_FF      4096
#define T_DIM     16384            // E * 2048
#define M_TOTAL   32768            // B * T

// ---------------- tiling ----------------
#define BM 128
#define BN 256
#define BK 32
#define STAGES 3
#define NTHREADS 256

#define A_LD 36                     // 32 + 4 pad (conflict-free frag loads)
#define B_LD 264                    // 256 + 8 pad
#define A_STG (BM * A_LD)           // 4608 floats
#define B_STG (BK * B_LD)           // 8448 floats
#define STG_FLOATS (A_STG + B_STG)  // 13056 floats
#define SMEM_BYTES (STAGES * STG_FLOATS * 4)   // 156672 B -> 1 CTA/SM

// ---------------- device scratch ----------------
__device__ float g_H  [(size_t)M_TOTAL * D_FF];              // 536 MB
__device__ float g_XR [(size_t)M_TOTAL * D_MODEL];           // tf32-rounded x
__device__ float g_W1R[(size_t)E_EXPERTS * D_MODEL * D_FF];  // tf32-rounded w1
__device__ float g_W2R[(size_t)E_EXPERTS * D_FF * D_MODEL];  // tf32-rounded w2

// ---------------- helpers ----------------
__device__ __forceinline__ uint32_t smem_u32(const void* p) {
    uint32_t a;
    asm("{ .reg .u64 t; cvta.to.shared.u64 t, %1; cvt.u32.u64 %0, t; }"
        : "=r"(a) : "l"(p));
    return a;
}
__device__ __forceinline__ void cp16(uint32_t s, const float* g) {
    asm volatile("cp.async.cg.shared.global [%0], [%1], 16;\n" :: "r"(s), "l"(g));
}
__device__ __forceinline__ void cp_commit() {
    asm volatile("cp.async.commit_group;\n" ::: "memory");
}
__device__ __forceinline__ void cp_wait1() {
    asm volatile("cp.async.wait_group 1;\n" ::: "memory");
}

__device__ __forceinline__ float tf32rn(float v) {
    uint32_t o;
    asm("cvt.rna.tf32.f32 %0, %1;" : "=r"(o) : "f"(v));
    return __uint_as_float(o);
}
__device__ __forceinline__ float gelu_erf(float v) {
    return 0.5f * v * (1.0f + erff(v * 0.7071067811865475f));
}

__device__ __forceinline__ void mma_tf32(float* c, const uint32_t* a,
                                         const uint32_t* b) {
    asm volatile(
        "mma.sync.aligned.m16n8k8.row.col.f32.tf32.tf32.f32 "
        "{%0,%1,%2,%3}, {%4,%5,%6,%7}, {%8,%9}, {%0,%1,%2,%3};"
        : "+f"(c[0]), "+f"(c[1]), "+f"(c[2]), "+f"(c[3])
        : "r"(a[0]), "r"(a[1]), "r"(a[2]), "r"(a[3]), "r"(b[0]), "r"(b[1]));
}

// ---------------- tf32 pre-round pass ----------------
// DSEL: 0 -> g_XR, 1 -> g_W1R, 2 -> g_W2R
template <int DSEL>
__global__ void round_tf32(const float* __restrict__ src, size_t n4) {
    float* dst = (DSEL == 0) ? g_XR : (DSEL == 1) ? g_W1R : g_W2R;
    const float4* s = (const float4*)src;
    float4* d = (float4*)dst;
    for (size_t i = (size_t)blockIdx.x * blockDim.x + threadIdx.x; i < n4;
         i += (size_t)gridDim.x * blockDim.x) {
        float4 v = s[i];
        v.x = tf32rn(v.x); v.y = tf32rn(v.y);
        v.z = tf32rn(v.z); v.w = tf32rn(v.w);
        d[i] = v;
    }
}

// ---------------- main mma.sync tf32 GEMM ----------------
// Out[m, n] = act( sum_k A[m,k] * W[e][k,n] + bias[e][n] )
// CTA tile 128x256, warp tile 64x64 (8 warps: 2 M-bands x 4 N-bands).
// Inner loop: double-buffered fragment registers — frag loads for ks+1 are
// issued before the MMAs of ks, hiding LDS latency behind tensor-pipe work.
template <bool GELU, int ASEL, int WSEL, bool OUT_H>
__global__ void __launch_bounds__(NTHREADS, 1)
ffn_mma(const float* __restrict__ bias, float* __restrict__ OutExt,
        int K, int Ntot)
{
    extern __shared__ float sm[];

    const int tid   = threadIdx.x;
    const int warp  = tid >> 5;
    const int lane  = tid & 31;
    const int warpM = warp >> 2;      // 0..1 : 64-row bands
    const int warpN = warp & 3;       // 0..3 : 64-col bands
    const int gq    = lane >> 2;      // 0..7
    const int lr    = lane & 3;       // 0..3

    const int n0 = blockIdx.x * BN;
    const int m0 = blockIdx.y * BM;
    const int e  = (m0 & (T_DIM - 1)) >> 11;

    const float* A = (ASEL == 0) ? g_XR : g_H;
    const float* W = (WSEL == 1) ? g_W1R : g_W2R;
    float* Out = OUT_H ? g_H : OutExt;

    const float* Abase = A + (size_t)m0 * K;
    const float* Wbase = W + (size_t)e * ((size_t)K * Ntot) + n0;

    // ---- stage loader (cp.async): A 128x32, B 32x256 ----
    auto load_stage = [&](int kt, int s) {
        float* Ad = sm + s * STG_FLOATS;
        float* Bd = Ad + A_STG;
        const float* Ag = Abase + (size_t)kt * BK;
        #pragma unroll
        for (int i = 0; i < 4; i++) {
            int cid = tid + i * NTHREADS;
            int row = cid >> 3, c4 = (cid & 7) << 2;
            cp16(smem_u32(Ad + row * A_LD + c4), Ag + (size_t)row * K + c4);
        }
        const float* Bg = Wbase + (size_t)(kt * BK) * Ntot;
        #pragma unroll
        for (int i = 0; i < 8; i++) {
            int cid = tid + i * NTHREADS;
            int row = cid >> 6, c4 = (cid & 63) << 2;
            cp16(smem_u32(Bd + row * B_LD + c4), Bg + (size_t)row * Ntot + c4);
        }
    };

    // ---- accumulators: warp tile 64x64 = 4 m-frags x 8 n-frags ----
    float acc[4][8][4];
    #pragma unroll
    for (int mi = 0; mi < 4; mi++)
        #pragma unroll
        for (int ni = 0; ni < 8; ni++)
            #pragma unroll
            for (int t = 0; t < 4; t++)
                acc[mi][ni][t] = 0.0f;

    const int KT = K / BK;

    load_stage(0, 0); cp_commit();
    load_stage(1, 1); cp_commit();

    const int aRow0 = warpM * 64 + gq;
    const int bCol0 = warpN * 64 + gq;

    // double-buffered fragment registers
    uint32_t fa[2][4][4];
    uint32_t fb[2][8][2];

#define LOAD_FRAGS(dst, ksv)                                             \
    do {                                                                 \
        const int kc_ = (ksv) * 8 + lr;                                  \
        _Pragma("unroll")                                                \
        for (int mi_ = 0; mi_ < 4; mi_++) {                              \
            int r_ = aRow0 + mi_ * 16;                                   \
            fa[dst][mi_][0] = As[r_ * A_LD + kc_];                       \
            fa[dst][mi_][1] = As[(r_ + 8) * A_LD + kc_];                 \
            fa[dst][mi_][2] = As[r_ * A_LD + kc_ + 4];                   \
            fa[dst][mi_][3] = As[(r_ + 8) * A_LD + kc_ + 4];             \
        }                                                                \
        _Pragma("unroll")                                                \
        for (int ni_ = 0; ni_ < 8; ni_++) {                              \
            int nn_ = bCol0 + ni_ * 8;                                   \
            fb[dst][ni_][0] = Bs[kc_ * B_LD + nn_];                      \
            fb[dst][ni_][1] = Bs[(kc_ + 4) * B_LD + nn_];                \
        }                                                                \
    } while (0)

    for (int kt = 0; kt < KT; ++kt) {
        cp_wait1();              // stage kt resident (one group always newer)
        __syncthreads();         // all warps done reading stage kt-1

        if (kt + 2 < KT) load_stage(kt + 2, (kt + 2) % STAGES);
        cp_commit();             // always commit: uniform group accounting

        const uint32_t* As = (const uint32_t*)(sm + (kt % STAGES) * STG_FLOATS);
        const uint32_t* Bs = As + A_STG;

        LOAD_FRAGS(0, 0);        // prime ks=0 fragments

        #pragma unroll
        for (int ks = 0; ks < 4; ks++) {
            const int cur = ks & 1;
            if (ks < 3) LOAD_FRAGS(cur ^ 1, ks + 1);   // prefetch next frags
            #pragma unroll
            for (int mi = 0; mi < 4; mi++)
                #pragma unroll
                for (int ni = 0; ni < 8; ni++)
                    mma_tf32(acc[mi][ni], fa[cur][mi], fb[cur][ni]);
        }
    }
#undef LOAD_FRAGS

    // ---- epilogue: direct STG, bias + optional erf-GELU ----
    const float* bptr = bias + (size_t)e * Ntot;
    float bb0[8], bb1[8];
    #pragma unroll
    for (int ni = 0; ni < 8; ni++) {
        int col = n0 + warpN * 64 + ni * 8 + lr * 2;
        bb0[ni] = __ldg(bptr + col);
        bb1[ni] = __ldg(bptr + col + 1);
    }
    #pragma unroll
    for (int mi = 0; mi < 4; mi++) {
        int r = m0 + warpM * 64 + mi * 16 + gq;
        #pragma unroll
        for (int ni = 0; ni < 8; ni++) {
            int col = n0 + warpN * 64 + ni * 8 + lr * 2;
            float v0 = acc[mi][ni][0] + bb0[ni];
            float v1 = acc[mi][ni][1] + bb1[ni];
            float v2 = acc[mi][ni][2] + bb0[ni];
            float v3 = acc[mi][ni][3] + bb1[ni];
            if (GELU) {
                v0 = gelu_erf(v0); v1 = gelu_erf(v1);
                v2 = gelu_erf(v2); v3 = gelu_erf(v3);
            }
            if (OUT_H) {         // feeds GEMM2's A: pre-round to tf32
                v0 = tf32rn(v0); v1 = tf32rn(v1);
                v2 = tf32rn(v2); v3 = tf32rn(v3);
            }
            float2 p0 = make_float2(v0, v1);
            float2 p1 = make_float2(v2, v3);
            *(float2*)&Out[(size_t)r * Ntot + col] = p0;
            *(float2*)&Out[(size_t)(r + 8) * Ntot + col] = p1;
        }
    }
}

// ---------------- host launcher ----------------
extern "C" void kernel_launch(void* const* d_in, const int* in_sizes, int n_in,
                              void* d_out, int out_size)
{
    (void)in_sizes; (void)n_in; (void)out_size;
    const float* x  = (const float*)d_in[0];
    const float* w1 = (const float*)d_in[1];
    const float* b1 = (const float*)d_in[2];
    const float* w2 = (const float*)d_in[3];
    const float* b2 = (const float*)d_in[4];
    float* out = (float*)d_out;

    cudaFuncSetAttribute(ffn_mma<true, 0, 1, true>,
                         cudaFuncAttributeMaxDynamicSharedMemorySize, SMEM_BYTES);
    cudaFuncSetAttribute(ffn_mma<false, 1, 2, false>,
                         cudaFuncAttributeMaxDynamicSharedMemorySize, SMEM_BYTES);

    // tf32 pre-round: x, w1, w2  (float4 grid-stride)
    const size_t nx4 = (size_t)M_TOTAL * D_MODEL / 4;                 // 8.39M
    const size_t nw4 = (size_t)E_EXPERTS * D_MODEL * D_FF / 4;        // 8.39M
    round_tf32<0><<<16384, 256>>>(x,  nx4);
    round_tf32<1><<<16384, 256>>>(w1, nw4);
    round_tf32<2><<<16384, 256>>>(w2, nw4);

    // GEMM1: g_XR [32768,1024] @ w1 -> bias + gelu -> g_H [32768,4096] (tf32)
    ffn_mma<true, 0, 1, true>
        <<<dim3(D_FF / BN, M_TOTAL / BM), NTHREADS, SMEM_BYTES>>>(
            b1, nullptr, D_MODEL, D_FF);
    // GEMM2: g_H [32768,4096] @ w2 + b2 -> out [32768,1024]
    ffn_mma<false, 1, 2, false>
        <<<dim3(D_MODEL / BN, M_TOTAL / BM), NTHREADS, SMEM_BYTES>>>(
            b2, out, D_FF, D_MODEL);
}

// round 15
// speedup vs baseline: 1.8380x; 1.8380x over previous
#include <cuda_runtime.h>
#include <cuda_fp16.h>
#include <cstdint>
#include <math.h>

// ---------------- problem constants ----------------
#define E_EXPERTS 8
#define D_MODEL   1024
#define D_FF      4096
#define T_DIM     16384            // E * 2048
#define M_TOTAL   32768            // B * T

// ---------------- tiling ----------------
#define BM 128
#define BN 256
#define BK 64                       // halves per K-slab
#define STAGES 3
#define NTHREADS 256

#define A_LDH 72                    // 64 + 8 pad halves -> 144B row stride
#define A_BYTES (BM * A_LDH * 2)    // 18432
#define B_BYTES (BN * A_LDH * 2)    // 36864
#define STG_BYTES (A_BYTES + B_BYTES)          // 55296
#define SMEM_BYTES (STAGES * STG_BYTES)        // 165888 -> 1 CTA/SM

// ---------------- device scratch ----------------
__device__ __half g_H  [(size_t)M_TOTAL * D_FF];               // 268 MB (half)
__device__ __half g_Xh [(size_t)M_TOTAL * D_MODEL];            // x as half
__device__ __half g_W1h[(size_t)E_EXPERTS * D_FF * D_MODEL];   // [E][F][D]
__device__ __half g_W2h[(size_t)E_EXPERTS * D_MODEL * D_FF];   // [E][D][F]

// ---------------- helpers ----------------
__device__ __forceinline__ uint32_t smem_u32(const void* p) {
    uint32_t a;
    asm("{ .reg .u64 t; cvta.to.shared.u64 t, %1; cvt.u32.u64 %0, t; }"
        : "=r"(a) : "l"(p));
    return a;
}
__device__ __forceinline__ void cp16(uint32_t s, const void* g) {
    asm volatile("cp.async.cg.shared.global [%0], [%1], 16;\n" :: "r"(s), "l"(g));
}
__device__ __forceinline__ void cp_commit() {
    asm volatile("cp.async.commit_group;\n" ::: "memory");
}
__device__ __forceinline__ void cp_wait1() {
    asm volatile("cp.async.wait_group 1;\n" ::: "memory");
}
__device__ __forceinline__ float gelu_erf(float v) {
    return 0.5f * v * (1.0f + erff(v * 0.7071067811865475f));
}
__device__ __forceinline__ void ldmat4(uint32_t* r, uint32_t addr) {
    asm volatile(
        "ldmatrix.sync.aligned.m8n8.x4.shared.b16 {%0,%1,%2,%3}, [%4];"
        : "=r"(r[0]), "=r"(r[1]), "=r"(r[2]), "=r"(r[3]) : "r"(addr));
}
__device__ __forceinline__ void mma_f16(float* c, const uint32_t* a,
                                        const uint32_t* b) {
    asm volatile(
        "mma.sync.aligned.m16n8k16.row.col.f32.f16.f16.f32 "
        "{%0,%1,%2,%3}, {%4,%5,%6,%7}, {%8,%9}, {%0,%1,%2,%3};"
        : "+f"(c[0]), "+f"(c[1]), "+f"(c[2]), "+f"(c[3])
        : "r"(a[0]), "r"(a[1]), "r"(a[2]), "r"(a[3]), "r"(b[0]), "r"(b[1]));
}

// ---------------- conversion pre-passes ----------------
// x [M, D] fp32 -> g_Xh half
__global__ void conv_x(const float* __restrict__ src, size_t n2) {
    __half2* d = (__half2*)g_Xh;
    const float2* s = (const float2*)src;
    for (size_t i = (size_t)blockIdx.x * blockDim.x + threadIdx.x; i < n2;
         i += (size_t)gridDim.x * blockDim.x) {
        float2 v = s[i];
        d[i] = __floats2half2_rn(v.x, v.y);
    }
}

// W [E][R][C] fp32 -> dst [E][C][R] half (transpose per expert)
template <int WSEL>
__global__ void transpose_h(const float* __restrict__ src, int R, int C) {
    __shared__ float t[32][33];
    __half* dst = (WSEL == 1) ? g_W1h : g_W2h;
    size_t eo = (size_t)blockIdx.z * (size_t)R * (size_t)C;
    const float* s = src + eo;
    __half* d = dst + eo;
    int c0 = blockIdx.x * 32, r0 = blockIdx.y * 32;
    int tx = threadIdx.x, ty = threadIdx.y;
    #pragma unroll
    for (int i = 0; i < 32; i += 8)
        t[ty + i][tx] = s[(size_t)(r0 + ty + i) * C + (c0 + tx)];
    __syncthreads();
    #pragma unroll
    for (int i = 0; i < 32; i += 8)
        d[(size_t)(c0 + ty + i) * R + (r0 + tx)] = __float2half(t[tx][ty + i]);
}

// ---------------- main fp16 mma GEMM ----------------
// Out[m, n] = act( sum_k A[m,k] * Wt[e][n,k] + bias[e][n] )
// A: ASEL 0 -> g_Xh [M,1024], 1 -> g_H [M,4096]  (half, row-major, k contig)
// Wt: WSEL 1 -> g_W1h [E][4096][1024], 2 -> g_W2h [E][1024][4096] (n-major, k contig)
// CTA tile 128x256, warp tile 64x64 (8 warps: 2 M-bands x 4 N-bands).
template <bool GELU, int ASEL, int WSEL, bool OUT_H>
__global__ void __launch_bounds__(NTHREADS, 1)
ffn_mma(const float* __restrict__ bias, float* __restrict__ OutExt,
        int K, int Ntot)
{
    extern __shared__ char smraw[];
    const uint32_t sb = smem_u32(smraw);

    const int tid   = threadIdx.x;
    const int warp  = tid >> 5;
    const int lane  = tid & 31;
    const int warpM = warp >> 2;      // 0..1 : 64-row bands
    const int warpN = warp & 3;       // 0..3 : 64-col bands
    const int gq    = lane >> 2;      // 0..7
    const int lr    = lane & 3;       // 0..3

    const int n0 = blockIdx.x * BN;
    const int m0 = blockIdx.y * BM;
    const int e  = (m0 & (T_DIM - 1)) >> 11;

    const __half* A  = (ASEL == 0) ? g_Xh : g_H;
    const __half* Wt = (WSEL == 1) ? g_W1h : g_W2h;

    const __half* Abase = A + (size_t)m0 * K;
    const __half* Bbase = Wt + (size_t)e * ((size_t)Ntot * K) + (size_t)n0 * K;

    // ---- stage loader (cp.async 16B): A 128x64h, B 256x64h ----
    auto load_stage = [&](int kt, int s) {
        const uint32_t aB = sb + s * STG_BYTES;
        const uint32_t bB = aB + A_BYTES;
        const __half* Ag = Abase + (size_t)kt * BK;
        #pragma unroll
        for (int i = 0; i < 4; i++) {
            int cid = tid + i * NTHREADS;
            int row = cid >> 3, c = cid & 7;
            cp16(aB + row * 144 + c * 16, Ag + (size_t)row * K + c * 8);
        }
        const __half* Bg = Bbase + (size_t)kt * BK;
        #pragma unroll
        for (int i = 0; i < 8; i++) {
            int cid = tid + i * NTHREADS;
            int row = cid >> 3, c = cid & 7;
            cp16(bB + row * 144 + c * 16, Bg + (size_t)row * K + c * 8);
        }
    };

    // ---- per-lane ldmatrix offsets (bytes within stage) ----
    // x4 ldmatrix: lane sel = lane>>3 picks matrix 0..3, lane&7 the row.
    const int sel = lane >> 3;
    // A (row-major m16xk16): mat0 rows0-7 k0-7, mat1 rows8-15 k0-7,
    //                        mat2 rows0-7 k8-15, mat3 rows8-15 k8-15
    uint32_t aoff[4];
    #pragma unroll
    for (int mi = 0; mi < 4; mi++)
        aoff[mi] = (uint32_t)((warpM * 64 + mi * 16 + ((sel & 1) << 3) +
                               (lane & 7)) * 144 + ((sel >> 1) << 4));
    // B ([n][k]): pair p covers ni=2p (mat0: n0-7 k0-7, mat1: n0-7 k8-15)
    //                       and ni=2p+1 (mat2: n8-15 k0-7, mat3: n8-15 k8-15)
    uint32_t boff[4];
    #pragma unroll
    for (int p = 0; p < 4; p++)
        boff[p] = (uint32_t)((warpN * 64 + p * 16 + ((sel >> 1) << 3) +
                              (lane & 7)) * 144 + ((sel & 1) << 4));

    // ---- accumulators: warp tile 64x64 = 4 m-frags x 8 n-frags ----
    float acc[4][8][4];
    #pragma unroll
    for (int mi = 0; mi < 4; mi++)
        #pragma unroll
        for (int ni = 0; ni < 8; ni++)
            #pragma unroll
            for (int t = 0; t < 4; t++)
                acc[mi][ni][t] = 0.0f;

    const int KT = K / BK;

    load_stage(0, 0); cp_commit();
    load_stage(1, 1); cp_commit();

    for (int kt = 0; kt < KT; ++kt) {
        cp_wait1();              // stage kt resident (one group always newer)
        __syncthreads();         // all warps done reading stage kt-1

        if (kt + 2 < KT) load_stage(kt + 2, (kt + 2) % STAGES);
        cp_commit();             // always commit: uniform group accounting

        const uint32_t aStage = sb + (kt % STAGES) * STG_BYTES;
        const uint32_t bStage = aStage + A_BYTES;

        #pragma unroll
        for (int ks = 0; ks < 4; ks++) {
            const uint32_t kb = ks * 32;           // 16 halves = 32 bytes
            uint32_t fa[4][4];
            #pragma unroll
            for (int mi = 0; mi < 4; mi++)
                ldmat4(fa[mi], aStage + aoff[mi] + kb);
            uint32_t fb[8][2];
            #pragma unroll
            for (int p = 0; p < 4; p++) {
                uint32_t q[4];
                ldmat4(q, bStage + boff[p] + kb);
                fb[2 * p][0] = q[0]; fb[2 * p][1] = q[1];
                fb[2 * p + 1][0] = q[2]; fb[2 * p + 1][1] = q[3];
            }
            #pragma unroll
            for (int mi = 0; mi < 4; mi++)
                #pragma unroll
                for (int ni = 0; ni < 8; ni++)
                    mma_f16(acc[mi][ni], fa[mi], fb[ni]);
        }
    }

    // ---- epilogue: bias + optional erf-GELU; half out (H) or fp32 out ----
    const float* bptr = bias + (size_t)e * Ntot;
    float bb0[8], bb1[8];
    #pragma unroll
    for (int ni = 0; ni < 8; ni++) {
        int col = n0 + warpN * 64 + ni * 8 + lr * 2;
        bb0[ni] = __ldg(bptr + col);
        bb1[ni] = __ldg(bptr + col + 1);
    }
    #pragma unroll
    for (int mi = 0; mi < 4; mi++) {
        int r = m0 + warpM * 64 + mi * 16 + gq;
        #pragma unroll
        for (int ni = 0; ni < 8; ni++) {
            int col = n0 + warpN * 64 + ni * 8 + lr * 2;
            float v0 = acc[mi][ni][0] + bb0[ni];
            float v1 = acc[mi][ni][1] + bb1[ni];
            float v2 = acc[mi][ni][2] + bb0[ni];
            float v3 = acc[mi][ni][3] + bb1[ni];
            if (GELU) {
                v0 = gelu_erf(v0); v1 = gelu_erf(v1);
                v2 = gelu_erf(v2); v3 = gelu_erf(v3);
            }
            if (OUT_H) {
                __half2* H2 = (__half2*)g_H;
                H2[((size_t)r * Ntot + col) >> 1] = __floats2half2_rn(v0, v1);
                H2[((size_t)(r + 8) * Ntot + col) >> 1] = __floats2half2_rn(v2, v3);
            } else {
                *(float2*)&OutExt[(size_t)r * Ntot + col] = make_float2(v0, v1);
                *(float2*)&OutExt[(size_t)(r + 8) * Ntot + col] = make_float2(v2, v3);
            }
        }
    }
}

// ---------------- host launcher ----------------
extern "C" void kernel_launch(void* const* d_in, const int* in_sizes, int n_in,
                              void* d_out, int out_size)
{
    (void)in_sizes; (void)n_in; (void)out_size;
    const float* x  = (const float*)d_in[0];
    const float* w1 = (const float*)d_in[1];
    const float* b1 = (const float*)d_in[2];
    const float* w2 = (const float*)d_in[3];
    const float* b2 = (const float*)d_in[4];
    float* out = (float*)d_out;

    cudaFuncSetAttribute(ffn_mma<true, 0, 1, true>,
                         cudaFuncAttributeMaxDynamicSharedMemorySize, SMEM_BYTES);
    cudaFuncSetAttribute(ffn_mma<false, 1, 2, false>,
                         cudaFuncAttributeMaxDynamicSharedMemorySize, SMEM_BYTES);

    // pre-passes: x -> half; w1,w2 -> transposed half [E][N][K]
    conv_x<<<8192, 256>>>(x, (size_t)M_TOTAL * D_MODEL / 2);
    dim3 tb(32, 8);
    transpose_h<1><<<dim3(D_FF / 32, D_MODEL / 32, E_EXPERTS), tb>>>(w1, D_MODEL, D_FF);
    transpose_h<2><<<dim3(D_MODEL / 32, D_FF / 32, E_EXPERTS), tb>>>(w2, D_FF, D_MODEL);

    // GEMM1: g_Xh [32768,1024] @ w1 -> bias + gelu -> g_H (half) [32768,4096]
    ffn_mma<true, 0, 1, true>
        <<<dim3(D_FF / BN, M_TOTAL / BM), NTHREADS, SMEM_BYTES>>>(
            b1, nullptr, D_MODEL, D_FF);
    // GEMM2: g_H [32768,4096] @ w2 + b2 -> out [32768,1024] fp32
    ffn_mma<false, 1, 2, false>
        <<<dim3(D_MODEL / BN, M_TOTAL / BM), NTHREADS, SMEM_BYTES>>>(
            b2, out, D_FF, D_MODEL);
}

// round 17
// speedup vs baseline: 1.9784x; 1.0764x over previous
#include <cuda_runtime.h>
#include <cuda_fp16.h>
#include <cstdint>
#include <math.h>

// ---------------- problem constants ----------------
#define E_EXPERTS 8
#define D_MODEL   1024
#define D_FF      4096
#define T_DIM     16384            // E * 2048
#define M_TOTAL   32768            // B * T

// ---------------- tiling ----------------
#define BM 128
#define BN 128
#define BK 64                       // halves per K-slab
#define STAGES 3
#define NTHREADS 256

#define A_LDH 72                    // 64 + 8 pad halves -> 144B row stride
#define A_BYTES (BM * A_LDH * 2)    // 18432
#define B_BYTES (BN * A_LDH * 2)    // 18432
#define STG_BYTES (A_BYTES + B_BYTES)          // 36864
#define SMEM_BYTES (STAGES * STG_BYTES)        // 110592 -> 2 CTAs/SM

// ---------------- device scratch ----------------
__device__ __half g_H  [(size_t)M_TOTAL * D_FF];               // 268 MB (half)
__device__ __half g_Xh [(size_t)M_TOTAL * D_MODEL];            // x as half
__device__ __half g_W1h[(size_t)E_EXPERTS * D_FF * D_MODEL];   // [E][F][D]
__device__ __half g_W2h[(size_t)E_EXPERTS * D_MODEL * D_FF];   // [E][D][F]

// ---------------- helpers ----------------
__device__ __forceinline__ uint32_t smem_u32(const void* p) {
    uint32_t a;
    asm("{ .reg .u64 t; cvta.to.shared.u64 t, %1; cvt.u32.u64 %0, t; }"
        : "=r"(a) : "l"(p));
    return a;
}
__device__ __forceinline__ void cp16(uint32_t s, const void* g) {
    asm volatile("cp.async.cg.shared.global [%0], [%1], 16;\n" :: "r"(s), "l"(g));
}
__device__ __forceinline__ void cp_commit() {
    asm volatile("cp.async.commit_group;\n" ::: "memory");
}
__device__ __forceinline__ void cp_wait1() {
    asm volatile("cp.async.wait_group 1;\n" ::: "memory");
}
__device__ __forceinline__ float gelu_erf(float v) {
    return 0.5f * v * (1.0f + erff(v * 0.7071067811865475f));
}
__device__ __forceinline__ void ldmat4(uint32_t* r, uint32_t addr) {
    asm volatile(
        "ldmatrix.sync.aligned.m8n8.x4.shared.b16 {%0,%1,%2,%3}, [%4];"
        : "=r"(r[0]), "=r"(r[1]), "=r"(r[2]), "=r"(r[3]) : "r"(addr));
}
__device__ __forceinline__ void mma_f16(float* c, const uint32_t* a,
                                        const uint32_t* b) {
    asm volatile(
        "mma.sync.aligned.m16n8k16.row.col.f32.f16.f16.f32 "
        "{%0,%1,%2,%3}, {%4,%5,%6,%7}, {%8,%9}, {%0,%1,%2,%3};"
        : "+f"(c[0]), "+f"(c[1]), "+f"(c[2]), "+f"(c[3])
        : "r"(a[0]), "r"(a[1]), "r"(a[2]), "r"(a[3]), "r"(b[0]), "r"(b[1]));
}

// ---------------- conversion pre-passes ----------------
// x [M, D] fp32 -> g_Xh half
__global__ void conv_x(const float* __restrict__ src, size_t n2) {
    __half2* d = (__half2*)g_Xh;
    const float2* s = (const float2*)src;
    for (size_t i = (size_t)blockIdx.x * blockDim.x + threadIdx.x; i < n2;
         i += (size_t)gridDim.x * blockDim.x) {
        float2 v = s[i];
        d[i] = __floats2half2_rn(v.x, v.y);
    }
}

// W [E][R][C] fp32 -> dst [E][C][R] half (transpose per expert)
template <int WSEL>
__global__ void transpose_h(const float* __restrict__ src, int R, int C) {
    __shared__ float t[32][33];
    __half* dst = (WSEL == 1) ? g_W1h : g_W2h;
    size_t eo = (size_t)blockIdx.z * (size_t)R * (size_t)C;
    const float* s = src + eo;
    __half* d = dst + eo;
    int c0 = blockIdx.x * 32, r0 = blockIdx.y * 32;
    int tx = threadIdx.x, ty = threadIdx.y;
    #pragma unroll
    for (int i = 0; i < 32; i += 8)
        t[ty + i][tx] = s[(size_t)(r0 + ty + i) * C + (c0 + tx)];
    __syncthreads();
    #pragma unroll
    for (int i = 0; i < 32; i += 8)
        d[(size_t)(c0 + ty + i) * R + (r0 + tx)] = __float2half(t[tx][ty + i]);
}

// ---------------- main fp16 mma GEMM ----------------
// Out[m, n] = act( sum_k A[m,k] * Wt[e][n,k] + bias[e][n] )
// A: ASEL 0 -> g_Xh [M,1024], 1 -> g_H [M,4096]  (half, row-major, k contig)
// Wt: WSEL 1 -> g_W1h [E][4096][1024], 2 -> g_W2h [E][1024][4096] (n-major, k contig)
// CTA tile 128x128, warp tile 64x32 (8 warps: 2 M-bands x 4 N-bands), 2 CTA/SM.
template <bool GELU, int ASEL, int WSEL, bool OUT_H>
__global__ void __launch_bounds__(NTHREADS, 2)
ffn_mma(const float* __restrict__ bias, float* __restrict__ OutExt,
        int K, int Ntot)
{
    extern __shared__ char smraw[];
    const uint32_t sb = smem_u32(smraw);

    const int tid   = threadIdx.x;
    const int warp  = tid >> 5;
    const int lane  = tid & 31;
    const int warpM = warp >> 2;      // 0..1 : 64-row bands
    const int warpN = warp & 3;       // 0..3 : 32-col bands
    const int gq    = lane >> 2;      // 0..7
    const int lr    = lane & 3;       // 0..3

    const int n0 = blockIdx.x * BN;
    const int m0 = blockIdx.y * BM;
    const int e  = (m0 & (T_DIM - 1)) >> 11;

    const __half* A  = (ASEL == 0) ? g_Xh : g_H;
    const __half* Wt = (WSEL == 1) ? g_W1h : g_W2h;

    const __half* Abase = A + (size_t)m0 * K;
    const __half* Bbase = Wt + (size_t)e * ((size_t)Ntot * K) + (size_t)n0 * K;

    // ---- stage loader (cp.async 16B): A 128x64h, B 128x64h ----
    auto load_stage = [&](int kt, int s) {
        const uint32_t aB = sb + s * STG_BYTES;
        const uint32_t bB = aB + A_BYTES;
        const __half* Ag = Abase + (size_t)kt * BK;
        #pragma unroll
        for (int i = 0; i < 4; i++) {
            int cid = tid + i * NTHREADS;
            int row = cid >> 3, c = cid & 7;
            cp16(aB + row * 144 + c * 16, Ag + (size_t)row * K + c * 8);
        }
        const __half* Bg = Bbase + (size_t)kt * BK;
        #pragma unroll
        for (int i = 0; i < 4; i++) {
            int cid = tid + i * NTHREADS;
            int row = cid >> 3, c = cid & 7;
            cp16(bB + row * 144 + c * 16, Bg + (size_t)row * K + c * 8);
        }
    };

    // ---- per-lane ldmatrix offsets (bytes within stage) ----
    const int sel = lane >> 3;        // x4 ldmatrix: matrix select 0..3
    // A (row-major m16xk16): mat0 rows0-7 k0-7, mat1 rows8-15 k0-7,
    //                        mat2 rows0-7 k8-15, mat3 rows8-15 k8-15
    uint32_t aoff[4];
    #pragma unroll
    for (int mi = 0; mi < 4; mi++)
        aoff[mi] = (uint32_t)((warpM * 64 + mi * 16 + ((sel & 1) << 3) +
                               (lane & 7)) * 144 + ((sel >> 1) << 4));
    // B ([n][k]): pair p covers ni=2p (mat0: n0-7 k0-7, mat1: n0-7 k8-15)
    //                       and ni=2p+1 (mat2: n8-15 k0-7, mat3: n8-15 k8-15)
    uint32_t boff[2];
    #pragma unroll
    for (int p = 0; p < 2; p++)
        boff[p] = (uint32_t)((warpN * 32 + p * 16 + ((sel >> 1) << 3) +
                              (lane & 7)) * 144 + ((sel & 1) << 4));

    // ---- accumulators: warp tile 64x32 = 4 m-frags x 4 n-frags ----
    float acc[4][4][4];
    #pragma unroll
    for (int mi = 0; mi < 4; mi++)
        #pragma unroll
        for (int ni = 0; ni < 4; ni++)
            #pragma unroll
            for (int t = 0; t < 4; t++)
                acc[mi][ni][t] = 0.0f;

    const int KT = K / BK;

    load_stage(0, 0); cp_commit();
    load_stage(1, 1); cp_commit();

    for (int kt = 0; kt < KT; ++kt) {
        cp_wait1();              // stage kt resident (one group always newer)
        __syncthreads();         // all warps done reading stage kt-1

        if (kt + 2 < KT) load_stage(kt + 2, (kt + 2) % STAGES);
        cp_commit();             // always commit: uniform group accounting

        const uint32_t aStage = sb + (kt % STAGES) * STG_BYTES;
        const uint32_t bStage = aStage + A_BYTES;

        #pragma unroll
        for (int ks = 0; ks < 4; ks++) {
            const uint32_t kb = ks * 32;           // 16 halves = 32 bytes
            uint32_t fa[4][4];
            #pragma unroll
            for (int mi = 0; mi < 4; mi++)
                ldmat4(fa[mi], aStage + aoff[mi] + kb);
            uint32_t fb[4][2];
            #pragma unroll
            for (int p = 0; p < 2; p++) {
                uint32_t q[4];
                ldmat4(q, bStage + boff[p] + kb);
                fb[2 * p][0] = q[0]; fb[2 * p][1] = q[1];
                fb[2 * p + 1][0] = q[2]; fb[2 * p + 1][1] = q[3];
            }
            #pragma unroll
            for (int mi = 0; mi < 4; mi++)
                #pragma unroll
                for (int ni = 0; ni < 4; ni++)
                    mma_f16(acc[mi][ni], fa[mi], fb[ni]);
        }
    }

    // ---- epilogue: bias + optional erf-GELU; half out (H) or fp32 out ----
    const float* bptr = bias + (size_t)e * Ntot;
    float bb0[4], bb1[4];
    #pragma unroll
    for (int ni = 0; ni < 4; ni++) {
        int col = n0 + warpN * 32 + ni * 8 + lr * 2;
        bb0[ni] = __ldg(bptr + col);
        bb1[ni] = __ldg(bptr + col + 1);
    }
    #pragma unroll
    for (int mi = 0; mi < 4; mi++) {
        int r = m0 + warpM * 64 + mi * 16 + gq;
        #pragma unroll
        for (int ni = 0; ni < 4; ni++) {
            int col = n0 + warpN * 32 + ni * 8 + lr * 2;
            float v0 = acc[mi][ni][0] + bb0[ni];
            float v1 = acc[mi][ni][1] + bb1[ni];
            float v2 = acc[mi][ni][2] + bb0[ni];
            float v3 = acc[mi][ni][3] + bb1[ni];
            if (GELU) {
                v0 = gelu_erf(v0); v1 = gelu_erf(v1);
                v2 = gelu_erf(v2); v3 = gelu_erf(v3);
            }
            if (OUT_H) {
                __half2* H2 = (__half2*)g_H;
                H2[((size_t)r * Ntot + col) >> 1] = __floats2half2_rn(v0, v1);
                H2[((size_t)(r + 8) * Ntot + col) >> 1] = __floats2half2_rn(v2, v3);
            } else {
                *(float2*)&OutExt[(size_t)r * Ntot + col] = make_float2(v0, v1);
                *(float2*)&OutExt[(size_t)(r + 8) * Ntot + col] = make_float2(v2, v3);
            }
        }
    }
}

// ---------------- host launcher ----------------
extern "C" void kernel_launch(void* const* d_in, const int* in_sizes, int n_in,
                              void* d_out, int out_size)
{
    (void)in_sizes; (void)n_in; (void)out_size;
    const float* x  = (const float*)d_in[0];
    const float* w1 = (const float*)d_in[1];
    const float* b1 = (const float*)d_in[2];
    const float* w2 = (const float*)d_in[3];
    const float* b2 = (const float*)d_in[4];
    float* out = (float*)d_out;

    cudaFuncSetAttribute(ffn_mma<true, 0, 1, true>,
                         cudaFuncAttributeMaxDynamicSharedMemorySize, SMEM_BYTES);
    cudaFuncSetAttribute(ffn_mma<false, 1, 2, false>,
                         cudaFuncAttributeMaxDynamicSharedMemorySize, SMEM_BYTES);

    // pre-passes: x -> half; w1,w2 -> transposed half [E][N][K]
    conv_x<<<8192, 256>>>(x, (size_t)M_TOTAL * D_MODEL / 2);
    dim3 tb(32, 8);
    transpose_h<1><<<dim3(D_FF / 32, D_MODEL / 32, E_EXPERTS), tb>>>(w1, D_MODEL, D_FF);
    transpose_h<2><<<dim3(D_MODEL / 32, D_FF / 32, E_EXPERTS), tb>>>(w2, D_FF, D_MODEL);

    // GEMM1: g_Xh [32768,1024] @ w1 -> bias + gelu -> g_H (half) [32768,4096]
    ffn_mma<true, 0, 1, true>
        <<<dim3(D_FF / BN, M_TOTAL / BM), NTHREADS, SMEM_BYTES>>>(
            b1, nullptr, D_MODEL, D_FF);
    // GEMM2: g_H [32768,4096] @ w2 + b2 -> out [32768,1024] fp32
    ffn_mma<false, 1, 2, false>
        <<<dim3(D_MODEL / BN, M_TOTAL / BM), NTHREADS, SMEM_BYTES>>>(
            b2, out, D_FF, D_MODEL);
}